// round 1
// baseline (speedup 1.0000x reference)
#include <cuda_runtime.h>
#include <math.h>

#define BB 2
#define SS 2048
#define DDIM 1024
#define HH 16
#define HDIM 64
#define FF 4096
#define MTOK (BB*SS)   /* 4096 rows */

// ---------------- scratch (static device arrays; no allocation) ----------------
__device__ float g_h  [MTOK*DDIM];   // LN output (reused for LN1 and LN2)
__device__ float g_q  [MTOK*DDIM];   // Q in (B,S,D) layout
__device__ float g_ctx[MTOK*DDIM];   // attention context in (B,S,D)
__device__ float g_x2 [MTOK*DDIM];   // post-attention residual
__device__ float g_ffn[MTOK*FF];     // gelu(h @ W1)

// ---------------- LayerNorm: one block per row, 256 threads ----------------
__global__ __launch_bounds__(256)
void ln_k(const float* __restrict__ x, const float* __restrict__ gg,
          const float* __restrict__ bb, float* __restrict__ out)
{
    __shared__ float red[32];
    int row = blockIdx.x;
    int tid = threadIdx.x;
    const float* xr = x + (size_t)row * DDIM;
    float4 v = *(const float4*)(xr + tid * 4);
    float s  = v.x + v.y + v.z + v.w;
    float s2 = v.x*v.x + v.y*v.y + v.z*v.z + v.w*v.w;
    #pragma unroll
    for (int off = 16; off; off >>= 1) {
        s  += __shfl_xor_sync(0xffffffffu, s,  off);
        s2 += __shfl_xor_sync(0xffffffffu, s2, off);
    }
    int warp = tid >> 5, lane = tid & 31;
    if (lane == 0) { red[warp] = s; red[warp + 8] = s2; }
    __syncthreads();
    if (tid == 0) {
        float ts = 0.f, ts2 = 0.f;
        #pragma unroll
        for (int w = 0; w < 8; ++w) { ts += red[w]; ts2 += red[w + 8]; }
        red[16] = ts; red[17] = ts2;
    }
    __syncthreads();
    float mean = red[16] * (1.0f / DDIM);
    float var  = red[17] * (1.0f / DDIM) - mean * mean;
    float inv  = rsqrtf(var + 1e-5f);
    float4 gv = *(const float4*)(gg + tid * 4);
    float4 bv = *(const float4*)(bb + tid * 4);
    float4 o;
    o.x = (v.x - mean) * inv * gv.x + bv.x;
    o.y = (v.y - mean) * inv * gv.y + bv.y;
    o.z = (v.z - mean) * inv * gv.z + bv.z;
    o.w = (v.w - mean) * inv * gv.w + bv.w;
    *(float4*)(out + (size_t)row * DDIM + tid * 4) = o;
}

// ---------------- SGEMM 128x128x16, 256 threads, 8x8 micro-tile ----------------
#define GBM 128
#define GBN 128
#define GBK 16
#define ASTRIDE (GBM + 4)   /* 132: keeps float4 alignment, reduces store conflicts */

#define EPI_NONE 0
#define EPI_BHSD 1
#define EPI_GELU 2
#define EPI_RES  3

__device__ __forceinline__ float gelu_exact(float x) {
    return 0.5f * x * (1.0f + erff(x * 0.70710678118654752f));
}

template<int EPI>
__global__ __launch_bounds__(256, 2)
void sgemm_k(const float* __restrict__ A, const float* __restrict__ W,
             float* __restrict__ C, const float* __restrict__ R,
             int N, int K)
{
    __shared__ float As[GBK][ASTRIDE];
    __shared__ float Bs[GBK][GBN];
    int tid = threadIdx.x;
    int tx = tid & 15, ty = tid >> 4;
    int bm = blockIdx.y * GBM;
    int bn = blockIdx.x * GBN;

    const float* Ab = A + (size_t)bm * K;
    const float* Wb = W + bn;

    int ar[2], ak[2], bk[2], bc[2];
    float4 aR[2], bR[2];
    #pragma unroll
    for (int p = 0; p < 2; ++p) {
        int idx = tid + p * 256;
        ar[p] = idx >> 2;        ak[p] = (idx & 3) * 4;
        bk[p] = idx >> 5;        bc[p] = (idx & 31) * 4;
        aR[p] = *(const float4*)(Ab + (size_t)ar[p] * K + ak[p]);
        bR[p] = *(const float4*)(Wb + (size_t)bk[p] * N + bc[p]);
    }

    float acc[8][8];
    #pragma unroll
    for (int i = 0; i < 8; ++i)
        #pragma unroll
        for (int j = 0; j < 8; ++j) acc[i][j] = 0.f;

    #pragma unroll
    for (int p = 0; p < 2; ++p) {
        As[ak[p] + 0][ar[p]] = aR[p].x;
        As[ak[p] + 1][ar[p]] = aR[p].y;
        As[ak[p] + 2][ar[p]] = aR[p].z;
        As[ak[p] + 3][ar[p]] = aR[p].w;
        *(float4*)&Bs[bk[p]][bc[p]] = bR[p];
    }
    __syncthreads();

    int T = K / GBK;
    for (int t = 0; t < T; ++t) {
        if (t + 1 < T) {
            int k0 = (t + 1) * GBK;
            #pragma unroll
            for (int p = 0; p < 2; ++p) {
                aR[p] = *(const float4*)(Ab + (size_t)ar[p] * K + k0 + ak[p]);
                bR[p] = *(const float4*)(Wb + (size_t)(k0 + bk[p]) * N + bc[p]);
            }
        }
        #pragma unroll
        for (int kk = 0; kk < GBK; ++kk) {
            float af[8], bf[8];
            *(float4*)&af[0] = *(const float4*)&As[kk][ty * 8];
            *(float4*)&af[4] = *(const float4*)&As[kk][ty * 8 + 4];
            *(float4*)&bf[0] = *(const float4*)&Bs[kk][tx * 8];
            *(float4*)&bf[4] = *(const float4*)&Bs[kk][tx * 8 + 4];
            #pragma unroll
            for (int i = 0; i < 8; ++i)
                #pragma unroll
                for (int j = 0; j < 8; ++j)
                    acc[i][j] = fmaf(af[i], bf[j], acc[i][j]);
        }
        __syncthreads();
        if (t + 1 < T) {
            #pragma unroll
            for (int p = 0; p < 2; ++p) {
                As[ak[p] + 0][ar[p]] = aR[p].x;
                As[ak[p] + 1][ar[p]] = aR[p].y;
                As[ak[p] + 2][ar[p]] = aR[p].z;
                As[ak[p] + 3][ar[p]] = aR[p].w;
                *(float4*)&Bs[bk[p]][bc[p]] = bR[p];
            }
            __syncthreads();
        }
    }

    // epilogue
    int r0 = bm + ty * 8;
    int c0 = bn + tx * 8;
    #pragma unroll
    for (int i = 0; i < 8; ++i) {
        int r = r0 + i;
        #pragma unroll
        for (int jj = 0; jj < 8; jj += 4) {
            int c = c0 + jj;
            float4 o;
            o.x = acc[i][jj + 0];
            o.y = acc[i][jj + 1];
            o.z = acc[i][jj + 2];
            o.w = acc[i][jj + 3];
            if (EPI == EPI_GELU) {
                o.x = gelu_exact(o.x); o.y = gelu_exact(o.y);
                o.z = gelu_exact(o.z); o.w = gelu_exact(o.w);
            }
            if (EPI == EPI_BHSD) {
                int b = r >> 11, s = r & 2047;
                int h = c >> 6,  hd = c & 63;
                size_t off = (((size_t)(b * HH + h)) * SS + s) * HDIM + hd;
                *(float4*)(C + off) = o;
            } else if (EPI == EPI_RES) {
                size_t off = (size_t)r * N + c;
                float4 rv = *(const float4*)(R + off);
                o.x += rv.x; o.y += rv.y; o.z += rv.z; o.w += rv.w;
                *(float4*)(C + off) = o;
            } else {
                *(float4*)(C + (size_t)r * N + c) = o;
            }
        }
    }
}

// ---------------- Flash attention (fp32, causal, 64q x 64k tiles) ----------------
#define FSTR 65
#define FLASH_SMEM (4 * 64 * FSTR * 4)   /* 66560 bytes */

__global__ __launch_bounds__(128)
void flash_k(const float* __restrict__ q, const float* __restrict__ kg,
             const float* __restrict__ vg, float* __restrict__ ctx)
{
    extern __shared__ float sm[];
    float* Qs = sm;
    float* Ks = Qs + 64 * FSTR;
    float* Vs = Ks + 64 * FSTR;
    float* Ps = Vs + 64 * FSTR;

    int qt = blockIdx.x;      // query tile 0..31
    int bh = blockIdx.y;      // 0..31
    int b = bh >> 4, h = bh & 15;
    int tid = threadIdx.x;
    int tx = tid & 15, ty = tid >> 4;   // ty in [0,8)

    const float* qb = q  + ((size_t)(b * SS + qt * 64)) * DDIM + h * HDIM;
    const float* kb = kg + (size_t)bh * SS * HDIM;
    const float* vb = vg + (size_t)bh * SS * HDIM;

    // load & pre-scale Q tile (64 x 64)
    for (int i = tid; i < 1024; i += 128) {
        int r = i >> 4, c = (i & 15) * 4;
        float4 v4 = *(const float4*)(qb + (size_t)r * DDIM + c);
        Qs[r * FSTR + c + 0] = v4.x * 0.125f;
        Qs[r * FSTR + c + 1] = v4.y * 0.125f;
        Qs[r * FSTR + c + 2] = v4.z * 0.125f;
        Qs[r * FSTR + c + 3] = v4.w * 0.125f;
    }

    float m[8], l[8], o[8][4];
    #pragma unroll
    for (int i = 0; i < 8; ++i) {
        m[i] = -1e30f; l[i] = 0.f;
        #pragma unroll
        for (int j = 0; j < 4; ++j) o[i][j] = 0.f;
    }
    __syncthreads();

    for (int kt = 0; kt <= qt; ++kt) {
        const float* kp = kb + (size_t)kt * 4096;
        const float* vp = vb + (size_t)kt * 4096;
        for (int i = tid; i < 1024; i += 128) {
            int r = i >> 4, c = (i & 15) * 4;
            float4 kv = *(const float4*)(kp + i * 4);
            Ks[r * FSTR + c + 0] = kv.x; Ks[r * FSTR + c + 1] = kv.y;
            Ks[r * FSTR + c + 2] = kv.z; Ks[r * FSTR + c + 3] = kv.w;
            float4 vv = *(const float4*)(vp + i * 4);
            Vs[r * FSTR + c + 0] = vv.x; Vs[r * FSTR + c + 1] = vv.y;
            Vs[r * FSTR + c + 2] = vv.z; Vs[r * FSTR + c + 3] = vv.w;
        }
        __syncthreads();

        float s[8][4];
        #pragma unroll
        for (int i = 0; i < 8; ++i)
            #pragma unroll
            for (int j = 0; j < 4; ++j) s[i][j] = 0.f;

        #pragma unroll 4
        for (int d = 0; d < 64; ++d) {
            float bb4[4], aa[8];
            #pragma unroll
            for (int j = 0; j < 4; ++j) bb4[j] = Ks[(tx * 4 + j) * FSTR + d];
            #pragma unroll
            for (int i = 0; i < 8; ++i) aa[i] = Qs[(ty * 8 + i) * FSTR + d];
            #pragma unroll
            for (int i = 0; i < 8; ++i)
                #pragma unroll
                for (int j = 0; j < 4; ++j)
                    s[i][j] = fmaf(aa[i], bb4[j], s[i][j]);
        }

        if (kt == qt) {
            #pragma unroll
            for (int i = 0; i < 8; ++i)
                #pragma unroll
                for (int j = 0; j < 4; ++j)
                    if (tx * 4 + j > ty * 8 + i) s[i][j] = -1e30f;
        }

        #pragma unroll
        for (int i = 0; i < 8; ++i) {
            float rm = fmaxf(fmaxf(s[i][0], s[i][1]), fmaxf(s[i][2], s[i][3]));
            rm = fmaxf(rm, __shfl_xor_sync(0xffffffffu, rm, 8));
            rm = fmaxf(rm, __shfl_xor_sync(0xffffffffu, rm, 4));
            rm = fmaxf(rm, __shfl_xor_sync(0xffffffffu, rm, 2));
            rm = fmaxf(rm, __shfl_xor_sync(0xffffffffu, rm, 1));
            float mnew = fmaxf(m[i], rm);
            float sc = __expf(m[i] - mnew);
            float rs = 0.f;
            #pragma unroll
            for (int j = 0; j < 4; ++j) {
                float p = __expf(s[i][j] - mnew);
                s[i][j] = p; rs += p;
                Ps[(ty * 8 + i) * FSTR + tx * 4 + j] = p;
            }
            rs += __shfl_xor_sync(0xffffffffu, rs, 8);
            rs += __shfl_xor_sync(0xffffffffu, rs, 4);
            rs += __shfl_xor_sync(0xffffffffu, rs, 2);
            rs += __shfl_xor_sync(0xffffffffu, rs, 1);
            l[i] = l[i] * sc + rs;
            m[i] = mnew;
            #pragma unroll
            for (int j = 0; j < 4; ++j) o[i][j] *= sc;
        }
        __syncthreads();

        #pragma unroll 4
        for (int kk = 0; kk < 64; ++kk) {
            float vv4[4], pv[8];
            #pragma unroll
            for (int j = 0; j < 4; ++j) vv4[j] = Vs[kk * FSTR + tx * 4 + j];
            #pragma unroll
            for (int i = 0; i < 8; ++i) pv[i] = Ps[(ty * 8 + i) * FSTR + kk];
            #pragma unroll
            for (int i = 0; i < 8; ++i)
                #pragma unroll
                for (int j = 0; j < 4; ++j)
                    o[i][j] = fmaf(pv[i], vv4[j], o[i][j]);
        }
        __syncthreads();
    }

    #pragma unroll
    for (int i = 0; i < 8; ++i) {
        int r = qt * 64 + ty * 8 + i;
        float invl = 1.0f / l[i];
        float4 ov;
        ov.x = o[i][0] * invl; ov.y = o[i][1] * invl;
        ov.z = o[i][2] * invl; ov.w = o[i][3] * invl;
        *(float4*)(ctx + ((size_t)(b * SS + r)) * DDIM + h * HDIM + tx * 4) = ov;
    }
}

// ---------------- launch ----------------
extern "C" void kernel_launch(void* const* d_in, const int* in_sizes, int n_in,
                              void* d_out, int out_size)
{
    const float* x    = (const float*)d_in[0];
    /* d_in[1] = attention_mask (pure causal; reproduced in-kernel) */
    const float* ln1g = (const float*)d_in[2];
    const float* ln1b = (const float*)d_in[3];
    const float* Wq   = (const float*)d_in[4];
    const float* Wk   = (const float*)d_in[5];
    const float* Wv   = (const float*)d_in[6];
    const float* Wo   = (const float*)d_in[7];
    const float* ln2g = (const float*)d_in[8];
    const float* ln2b = (const float*)d_in[9];
    const float* W1   = (const float*)d_in[10];
    const float* W2   = (const float*)d_in[11];

    float* out  = (float*)d_out;
    float* kout = out  + (size_t)MTOK * DDIM;
    float* vout = kout + (size_t)MTOK * DDIM;

    float *h, *qs, *ctx, *x2, *ffn;
    cudaGetSymbolAddress((void**)&h,   g_h);
    cudaGetSymbolAddress((void**)&qs,  g_q);
    cudaGetSymbolAddress((void**)&ctx, g_ctx);
    cudaGetSymbolAddress((void**)&x2,  g_x2);
    cudaGetSymbolAddress((void**)&ffn, g_ffn);

    cudaFuncSetAttribute(flash_k, cudaFuncAttributeMaxDynamicSharedMemorySize,
                         FLASH_SMEM);

    dim3 gQKV(DDIM / GBN, MTOK / GBM);   // (8, 32)
    dim3 gFFN(FF   / GBN, MTOK / GBM);   // (32, 32)

    // 1) LN1
    ln_k<<<MTOK, 256>>>(x, ln1g, ln1b, h);
    // 2-4) Q,K,V projections (K,V straight into d_out in (B,H,S,HD) layout)
    sgemm_k<EPI_NONE><<<gQKV, 256>>>(h, Wq, qs,   nullptr, DDIM, DDIM);
    sgemm_k<EPI_BHSD><<<gQKV, 256>>>(h, Wk, kout, nullptr, DDIM, DDIM);
    sgemm_k<EPI_BHSD><<<gQKV, 256>>>(h, Wv, vout, nullptr, DDIM, DDIM);
    // 5) causal flash attention, writes ctx in (B,S,D)
    flash_k<<<dim3(SS / 64, BB * HH), 128, FLASH_SMEM>>>(qs, kout, vout, ctx);
    // 6) output projection + residual
    sgemm_k<EPI_RES><<<gQKV, 256>>>(ctx, Wo, x2, x, DDIM, DDIM);
    // 7) LN2
    ln_k<<<MTOK, 256>>>(x2, ln2g, ln2b, h);
    // 8) FFN up + exact gelu
    sgemm_k<EPI_GELU><<<gFFN, 256>>>(h, W1, ffn, nullptr, FF, DDIM);
    // 9) FFN down + residual -> out
    sgemm_k<EPI_RES><<<gQKV, 256>>>(ffn, W2, out, x2, DDIM, FF);
}

// round 2
// speedup vs baseline: 1.0592x; 1.0592x over previous
#include <cuda_runtime.h>
#include <math.h>

#define BB 2
#define SS 2048
#define DDIM 1024
#define HH 16
#define HDIM 64
#define FF 4096
#define MTOK (BB*SS)   /* 4096 rows */

// ---------------- scratch (static device arrays; no allocation) ----------------
__device__ float g_h  [MTOK*DDIM];   // LN output (reused for LN1 and LN2)
__device__ float g_q  [MTOK*DDIM];   // Q in (B,S,D) layout
__device__ float g_ctx[MTOK*DDIM];   // attention context in (B,S,D)
__device__ float g_x2 [MTOK*DDIM];   // post-attention residual
__device__ float g_ffn[MTOK*FF];     // gelu(h @ W1)

// ---------------- packed f32x2 helpers (sm_103a FFMA2 path) ----------------
__device__ __forceinline__ unsigned long long ffma2(unsigned long long a,
                                                    unsigned long long b,
                                                    unsigned long long c)
{
    unsigned long long d;
    asm("fma.rn.f32x2 %0, %1, %2, %3;" : "=l"(d) : "l"(a), "l"(b), "l"(c));
    return d;
}
__device__ __forceinline__ unsigned long long dup2(float x)
{
    unsigned long long d;
    unsigned int xi = __float_as_uint(x);
    asm("mov.b64 %0, {%1, %1};" : "=l"(d) : "r"(xi));
    return d;
}
__device__ __forceinline__ float lo2(unsigned long long v)
{
    return __uint_as_float((unsigned int)(v & 0xffffffffull));
}
__device__ __forceinline__ float hi2(unsigned long long v)
{
    return __uint_as_float((unsigned int)(v >> 32));
}

// ---------------- LayerNorm: one block per row, 256 threads ----------------
__global__ __launch_bounds__(256)
void ln_k(const float* __restrict__ x, const float* __restrict__ gg,
          const float* __restrict__ bb, float* __restrict__ out)
{
    __shared__ float red[32];
    int row = blockIdx.x;
    int tid = threadIdx.x;
    const float* xr = x + (size_t)row * DDIM;
    float4 v = *(const float4*)(xr + tid * 4);
    float s  = v.x + v.y + v.z + v.w;
    float s2 = v.x*v.x + v.y*v.y + v.z*v.z + v.w*v.w;
    #pragma unroll
    for (int off = 16; off; off >>= 1) {
        s  += __shfl_xor_sync(0xffffffffu, s,  off);
        s2 += __shfl_xor_sync(0xffffffffu, s2, off);
    }
    int warp = tid >> 5, lane = tid & 31;
    if (lane == 0) { red[warp] = s; red[warp + 8] = s2; }
    __syncthreads();
    if (tid == 0) {
        float ts = 0.f, ts2 = 0.f;
        #pragma unroll
        for (int w = 0; w < 8; ++w) { ts += red[w]; ts2 += red[w + 8]; }
        red[16] = ts; red[17] = ts2;
    }
    __syncthreads();
    float mean = red[16] * (1.0f / DDIM);
    float var  = red[17] * (1.0f / DDIM) - mean * mean;
    float inv  = rsqrtf(var + 1e-5f);
    float4 gv = *(const float4*)(gg + tid * 4);
    float4 bv = *(const float4*)(bb + tid * 4);
    float4 o;
    o.x = (v.x - mean) * inv * gv.x + bv.x;
    o.y = (v.y - mean) * inv * gv.y + bv.y;
    o.z = (v.z - mean) * inv * gv.z + bv.z;
    o.w = (v.w - mean) * inv * gv.w + bv.w;
    *(float4*)(out + (size_t)row * DDIM + tid * 4) = o;
}

// ---------------- SGEMM 128x128x16, 256 threads, 8x8 micro-tile, FFMA2 ----------------
#define GBM 128
#define GBN 128
#define GBK 16
#define ASTRIDE (GBM + 4)   /* 132: keeps float4 alignment, reduces store conflicts */

#define EPI_NONE 0
#define EPI_BHSD 1
#define EPI_GELU 2
#define EPI_RES  3

__device__ __forceinline__ float gelu_exact(float x) {
    return 0.5f * x * (1.0f + erff(x * 0.70710678118654752f));
}

template<int EPI>
__global__ __launch_bounds__(256, 2)
void sgemm_k(const float* __restrict__ A, const float* __restrict__ W,
             float* __restrict__ C, const float* __restrict__ R,
             int N, int K)
{
    __shared__ float As[GBK][ASTRIDE];
    __shared__ float Bs[GBK][GBN];
    int tid = threadIdx.x;
    int tx = tid & 15, ty = tid >> 4;
    int bm = blockIdx.y * GBM;
    int bn = blockIdx.x * GBN;

    const float* Ab = A + (size_t)bm * K;
    const float* Wb = W + bn;

    int ar[2], ak[2], bk[2], bc[2];
    float4 aR[2], bR[2];
    #pragma unroll
    for (int p = 0; p < 2; ++p) {
        int idx = tid + p * 256;
        ar[p] = idx >> 2;        ak[p] = (idx & 3) * 4;
        bk[p] = idx >> 5;        bc[p] = (idx & 31) * 4;
        aR[p] = *(const float4*)(Ab + (size_t)ar[p] * K + ak[p]);
        bR[p] = *(const float4*)(Wb + (size_t)bk[p] * N + bc[p]);
    }

    // packed accumulators: acc2[i][j] holds columns (2j, 2j+1) of row i
    unsigned long long acc2[8][4];
    #pragma unroll
    for (int i = 0; i < 8; ++i)
        #pragma unroll
        for (int j = 0; j < 4; ++j) acc2[i][j] = 0ull;

    #pragma unroll
    for (int p = 0; p < 2; ++p) {
        As[ak[p] + 0][ar[p]] = aR[p].x;
        As[ak[p] + 1][ar[p]] = aR[p].y;
        As[ak[p] + 2][ar[p]] = aR[p].z;
        As[ak[p] + 3][ar[p]] = aR[p].w;
        *(float4*)&Bs[bk[p]][bc[p]] = bR[p];
    }
    __syncthreads();

    int T = K / GBK;
    for (int t = 0; t < T; ++t) {
        if (t + 1 < T) {
            int k0 = (t + 1) * GBK;
            #pragma unroll
            for (int p = 0; p < 2; ++p) {
                aR[p] = *(const float4*)(Ab + (size_t)ar[p] * K + k0 + ak[p]);
                bR[p] = *(const float4*)(Wb + (size_t)(k0 + bk[p]) * N + bc[p]);
            }
        }
        #pragma unroll
        for (int kk = 0; kk < GBK; ++kk) {
            float af[8];
            *(float4*)&af[0] = *(const float4*)&As[kk][ty * 8];
            *(float4*)&af[4] = *(const float4*)&As[kk][ty * 8 + 4];
            unsigned long long b2[4];
            const unsigned long long* bp =
                (const unsigned long long*)&Bs[kk][tx * 8];
            b2[0] = bp[0]; b2[1] = bp[1]; b2[2] = bp[2]; b2[3] = bp[3];
            #pragma unroll
            for (int i = 0; i < 8; ++i) {
                unsigned long long a2 = dup2(af[i]);
                #pragma unroll
                for (int j = 0; j < 4; ++j)
                    acc2[i][j] = ffma2(a2, b2[j], acc2[i][j]);
            }
        }
        __syncthreads();
        if (t + 1 < T) {
            #pragma unroll
            for (int p = 0; p < 2; ++p) {
                As[ak[p] + 0][ar[p]] = aR[p].x;
                As[ak[p] + 1][ar[p]] = aR[p].y;
                As[ak[p] + 2][ar[p]] = aR[p].z;
                As[ak[p] + 3][ar[p]] = aR[p].w;
                *(float4*)&Bs[bk[p]][bc[p]] = bR[p];
            }
            __syncthreads();
        }
    }

    // epilogue
    int r0 = bm + ty * 8;
    int c0 = bn + tx * 8;
    #pragma unroll
    for (int i = 0; i < 8; ++i) {
        int r = r0 + i;
        #pragma unroll
        for (int jj = 0; jj < 2; ++jj) {
            int c = c0 + jj * 4;
            float4 o;
            o.x = lo2(acc2[i][jj * 2 + 0]);
            o.y = hi2(acc2[i][jj * 2 + 0]);
            o.z = lo2(acc2[i][jj * 2 + 1]);
            o.w = hi2(acc2[i][jj * 2 + 1]);
            if (EPI == EPI_GELU) {
                o.x = gelu_exact(o.x); o.y = gelu_exact(o.y);
                o.z = gelu_exact(o.z); o.w = gelu_exact(o.w);
            }
            if (EPI == EPI_BHSD) {
                int b = r >> 11, s = r & 2047;
                int h = c >> 6,  hd = c & 63;
                size_t off = (((size_t)(b * HH + h)) * SS + s) * HDIM + hd;
                *(float4*)(C + off) = o;
            } else if (EPI == EPI_RES) {
                size_t off = (size_t)r * N + c;
                float4 rv = *(const float4*)(R + off);
                o.x += rv.x; o.y += rv.y; o.z += rv.z; o.w += rv.w;
                *(float4*)(C + off) = o;
            } else {
                *(float4*)(C + (size_t)r * N + c) = o;
            }
        }
    }
}

// ---------------- Flash attention (fp32, causal, 64q x 64k tiles) ----------------
#define FSTR 65
#define FLASH_SMEM (4 * 64 * FSTR * 4)   /* 66560 bytes */

__global__ __launch_bounds__(128)
void flash_k(const float* __restrict__ q, const float* __restrict__ kg,
             const float* __restrict__ vg, float* __restrict__ ctx)
{
    extern __shared__ float sm[];
    float* Qs = sm;
    float* Ks = Qs + 64 * FSTR;
    float* Vs = Ks + 64 * FSTR;
    float* Ps = Vs + 64 * FSTR;

    int qt = blockIdx.x;      // query tile 0..31
    int bh = blockIdx.y;      // 0..31
    int b = bh >> 4, h = bh & 15;
    int tid = threadIdx.x;
    int tx = tid & 15, ty = tid >> 4;   // ty in [0,8)

    const float* qb = q  + ((size_t)(b * SS + qt * 64)) * DDIM + h * HDIM;
    const float* kb = kg + (size_t)bh * SS * HDIM;
    const float* vb = vg + (size_t)bh * SS * HDIM;

    // load & pre-scale Q tile (64 x 64)
    for (int i = tid; i < 1024; i += 128) {
        int r = i >> 4, c = (i & 15) * 4;
        float4 v4 = *(const float4*)(qb + (size_t)r * DDIM + c);
        Qs[r * FSTR + c + 0] = v4.x * 0.125f;
        Qs[r * FSTR + c + 1] = v4.y * 0.125f;
        Qs[r * FSTR + c + 2] = v4.z * 0.125f;
        Qs[r * FSTR + c + 3] = v4.w * 0.125f;
    }

    float m[8], l[8], o[8][4];
    #pragma unroll
    for (int i = 0; i < 8; ++i) {
        m[i] = -1e30f; l[i] = 0.f;
        #pragma unroll
        for (int j = 0; j < 4; ++j) o[i][j] = 0.f;
    }
    __syncthreads();

    for (int kt = 0; kt <= qt; ++kt) {
        const float* kp = kb + (size_t)kt * 4096;
        const float* vp = vb + (size_t)kt * 4096;
        for (int i = tid; i < 1024; i += 128) {
            int r = i >> 4, c = (i & 15) * 4;
            float4 kv = *(const float4*)(kp + i * 4);
            Ks[r * FSTR + c + 0] = kv.x; Ks[r * FSTR + c + 1] = kv.y;
            Ks[r * FSTR + c + 2] = kv.z; Ks[r * FSTR + c + 3] = kv.w;
            float4 vv = *(const float4*)(vp + i * 4);
            Vs[r * FSTR + c + 0] = vv.x; Vs[r * FSTR + c + 1] = vv.y;
            Vs[r * FSTR + c + 2] = vv.z; Vs[r * FSTR + c + 3] = vv.w;
        }
        __syncthreads();

        float s[8][4];
        #pragma unroll
        for (int i = 0; i < 8; ++i)
            #pragma unroll
            for (int j = 0; j < 4; ++j) s[i][j] = 0.f;

        #pragma unroll 4
        for (int d = 0; d < 64; ++d) {
            float bb4[4], aa[8];
            #pragma unroll
            for (int j = 0; j < 4; ++j) bb4[j] = Ks[(tx * 4 + j) * FSTR + d];
            #pragma unroll
            for (int i = 0; i < 8; ++i) aa[i] = Qs[(ty * 8 + i) * FSTR + d];
            #pragma unroll
            for (int i = 0; i < 8; ++i)
                #pragma unroll
                for (int j = 0; j < 4; ++j)
                    s[i][j] = fmaf(aa[i], bb4[j], s[i][j]);
        }

        if (kt == qt) {
            #pragma unroll
            for (int i = 0; i < 8; ++i)
                #pragma unroll
                for (int j = 0; j < 4; ++j)
                    if (tx * 4 + j > ty * 8 + i) s[i][j] = -1e30f;
        }

        #pragma unroll
        for (int i = 0; i < 8; ++i) {
            float rm = fmaxf(fmaxf(s[i][0], s[i][1]), fmaxf(s[i][2], s[i][3]));
            rm = fmaxf(rm, __shfl_xor_sync(0xffffffffu, rm, 8));
            rm = fmaxf(rm, __shfl_xor_sync(0xffffffffu, rm, 4));
            rm = fmaxf(rm, __shfl_xor_sync(0xffffffffu, rm, 2));
            rm = fmaxf(rm, __shfl_xor_sync(0xffffffffu, rm, 1));
            float mnew = fmaxf(m[i], rm);
            float sc = __expf(m[i] - mnew);
            float rs = 0.f;
            #pragma unroll
            for (int j = 0; j < 4; ++j) {
                float p = __expf(s[i][j] - mnew);
                s[i][j] = p; rs += p;
                Ps[(ty * 8 + i) * FSTR + tx * 4 + j] = p;
            }
            rs += __shfl_xor_sync(0xffffffffu, rs, 8);
            rs += __shfl_xor_sync(0xffffffffu, rs, 4);
            rs += __shfl_xor_sync(0xffffffffu, rs, 2);
            rs += __shfl_xor_sync(0xffffffffu, rs, 1);
            l[i] = l[i] * sc + rs;
            m[i] = mnew;
            #pragma unroll
            for (int j = 0; j < 4; ++j) o[i][j] *= sc;
        }
        __syncthreads();

        #pragma unroll 4
        for (int kk = 0; kk < 64; ++kk) {
            float vv4[4], pv[8];
            #pragma unroll
            for (int j = 0; j < 4; ++j) vv4[j] = Vs[kk * FSTR + tx * 4 + j];
            #pragma unroll
            for (int i = 0; i < 8; ++i) pv[i] = Ps[(ty * 8 + i) * FSTR + kk];
            #pragma unroll
            for (int i = 0; i < 8; ++i)
                #pragma unroll
                for (int j = 0; j < 4; ++j)
                    o[i][j] = fmaf(pv[i], vv4[j], o[i][j]);
        }
        __syncthreads();
    }

    #pragma unroll
    for (int i = 0; i < 8; ++i) {
        int r = qt * 64 + ty * 8 + i;
        float invl = 1.0f / l[i];
        float4 ov;
        ov.x = o[i][0] * invl; ov.y = o[i][1] * invl;
        ov.z = o[i][2] * invl; ov.w = o[i][3] * invl;
        *(float4*)(ctx + ((size_t)(b * SS + r)) * DDIM + h * HDIM + tx * 4) = ov;
    }
}

// ---------------- launch ----------------
extern "C" void kernel_launch(void* const* d_in, const int* in_sizes, int n_in,
                              void* d_out, int out_size)
{
    const float* x    = (const float*)d_in[0];
    /* d_in[1] = attention_mask (pure causal; reproduced in-kernel) */
    const float* ln1g = (const float*)d_in[2];
    const float* ln1b = (const float*)d_in[3];
    const float* Wq   = (const float*)d_in[4];
    const float* Wk   = (const float*)d_in[5];
    const float* Wv   = (const float*)d_in[6];
    const float* Wo   = (const float*)d_in[7];
    const float* ln2g = (const float*)d_in[8];
    const float* ln2b = (const float*)d_in[9];
    const float* W1   = (const float*)d_in[10];
    const float* W2   = (const float*)d_in[11];

    float* out  = (float*)d_out;
    float* kout = out  + (size_t)MTOK * DDIM;
    float* vout = kout + (size_t)MTOK * DDIM;

    float *h, *qs, *ctx, *x2, *ffn;
    cudaGetSymbolAddress((void**)&h,   g_h);
    cudaGetSymbolAddress((void**)&qs,  g_q);
    cudaGetSymbolAddress((void**)&ctx, g_ctx);
    cudaGetSymbolAddress((void**)&x2,  g_x2);
    cudaGetSymbolAddress((void**)&ffn, g_ffn);

    cudaFuncSetAttribute(flash_k, cudaFuncAttributeMaxDynamicSharedMemorySize,
                         FLASH_SMEM);

    dim3 gQKV(DDIM / GBN, MTOK / GBM);   // (8, 32)
    dim3 gFFN(FF   / GBN, MTOK / GBM);   // (32, 32)

    // 1) LN1
    ln_k<<<MTOK, 256>>>(x, ln1g, ln1b, h);
    // 2-4) Q,K,V projections (K,V straight into d_out in (B,H,S,HD) layout)
    sgemm_k<EPI_NONE><<<gQKV, 256>>>(h, Wq, qs,   nullptr, DDIM, DDIM);
    sgemm_k<EPI_BHSD><<<gQKV, 256>>>(h, Wk, kout, nullptr, DDIM, DDIM);
    sgemm_k<EPI_BHSD><<<gQKV, 256>>>(h, Wv, vout, nullptr, DDIM, DDIM);
    // 5) causal flash attention, writes ctx in (B,S,D)
    flash_k<<<dim3(SS / 64, BB * HH), 128, FLASH_SMEM>>>(qs, kout, vout, ctx);
    // 6) output projection + residual
    sgemm_k<EPI_RES><<<gQKV, 256>>>(ctx, Wo, x2, x, DDIM, DDIM);
    // 7) LN2
    ln_k<<<MTOK, 256>>>(x2, ln2g, ln2b, h);
    // 8) FFN up + exact gelu
    sgemm_k<EPI_GELU><<<gFFN, 256>>>(h, W1, ffn, nullptr, FF, DDIM);
    // 9) FFN down + residual -> out
    sgemm_k<EPI_RES><<<gQKV, 256>>>(ffn, W2, out, x2, DDIM, FF);
}